// round 1
// baseline (speedup 1.0000x reference)
#include <cuda_runtime.h>
#include <cstdint>
#include <cstring>

#define NTOK      65536
#define NE        512
#define VDIM      128
#define TOK_TILE  128
#define OUT_TILE  128
#define TILES_X   128

// Static scratch (no allocs allowed): bucket lists + padded counters.
__device__ int g_cnt[6 * 32];
__device__ int g_bucket[6][NTOK];

__global__ void zero_counts_kernel() {
    if (threadIdx.x < 6 * 32) g_cnt[threadIdx.x] = 0;
}

// Warp-aggregated bucketing: one atomic per (warp, type) instead of per token.
__global__ void bucket_kernel(const int* __restrict__ ttype) {
    int i = blockIdx.x * blockDim.x + threadIdx.x;   // grid exactly covers NTOK
    int t = ttype[i];
    t = t < 0 ? 0 : (t > 5 ? 5 : t);                 // safety clamp (inputs are 0..5)
    unsigned mask = __match_any_sync(0xffffffffu, t);
    int lane   = threadIdx.x & 31;
    int leader = __ffs(mask) - 1;
    int base = 0;
    if (lane == leader) base = atomicAdd(&g_cnt[t * 32], __popc(mask));
    base = __shfl_sync(mask, base, leader);
    g_bucket[t][base + __popc(mask & ((1u << lane) - 1u))] = i;
}

// ---------------------------------------------------------------------------
// Per-type GEMM: out[tok, ob+e] = type_emb[t][ob+e] + b[ob+e] + sum_k W[e,k]*v[tok,k]
// CTA tile: 128 tokens x 128 outputs. 512 threads, each 8 tok x 4 out.
// f32x2 accumulators pair (even k, odd k) partial sums -> no smem transpose needed.
// Smem row stride S = D+2 (== 2 mod 4) -> conflict-free LDS.64 on the W fragment.
// ---------------------------------------------------------------------------
template <int D>
__device__ __forceinline__ void compute_type(
    int t,
    const float* __restrict__ val,
    const float* __restrict__ temb,
    const float* __restrict__ W,
    const float* __restrict__ bias,
    float* __restrict__ out,
    float* sm)
{
    constexpr int KP = (D + 1) / 2;          // k-pairs
    constexpr int S  = (D == 1) ? 2 : (D + 2);

    float* Vs  = sm;                          // [TOK_TILE][S]
    float* Ws  = sm + TOK_TILE * S;           // [OUT_TILE][S]
    float* cb  = sm + 2 * TOK_TILE * S;       // [OUT_TILE]
    int*   sIdx = (int*)(cb + OUT_TILE);      // [TOK_TILE]

    const int n = g_cnt[t * 32];
    if (blockIdx.x * TOK_TILE >= n) return;   // uniform per block: safe early exit

    const int tid = threadIdx.x;
    const int tx  = tid & 31;                 // output lane: e = tx + 32*c
    const int ty  = tid >> 5;                 // token group: j = ty*8 + jj
    const int ob  = blockIdx.y * OUT_TILE;
    const int* __restrict__ bucket = g_bucket[t];

    // ---- Load W tile once per CTA (hoisted over the token-tile loop) ----
    if (D == 1) {
        for (int e = tid; e < OUT_TILE; e += 512) {
            Ws[e * S + 0] = W[ob + e];
            Ws[e * S + 1] = 0.f;
        }
    } else {
        constexpr int HP = D / 2;
        for (int i = tid; i < OUT_TILE * HP; i += 512) {
            int e  = i / HP;
            int kp = i - e * HP;
            *(float2*)&Ws[e * S + kp * 2] =
                *(const float2*)&W[(size_t)(ob + e) * D + kp * 2];
        }
    }
    // Combined bias: type_emb + b
    for (int e = tid; e < OUT_TILE; e += 512)
        cb[e] = temb[t * NE + ob + e] + bias[ob + e];

    for (int tile = blockIdx.x; tile * TOK_TILE < n; tile += TILES_X) {
        __syncthreads();   // protect Vs/sIdx reuse from previous iteration

        if (tid < TOK_TILE) {
            int p = tile * TOK_TILE + tid;
            sIdx[tid] = bucket[p < n ? p : 0];
        }
        // ---- Gather value tile (padded lanes duplicate bucket[0]: benign) ----
        if (D == 1) {
            for (int j = tid; j < TOK_TILE; j += 512) {
                int p   = tile * TOK_TILE + j;
                int row = bucket[p < n ? p : 0];
                Vs[j * S + 0] = val[(size_t)row * VDIM];
                Vs[j * S + 1] = 0.f;
            }
        } else {
            constexpr int HP = D / 2;
            for (int i = tid; i < TOK_TILE * HP; i += 512) {
                int j  = i / HP;
                int kp = i - j * HP;
                int p   = tile * TOK_TILE + j;
                int row = bucket[p < n ? p : 0];
                *(float2*)&Vs[j * S + kp * 2] =
                    *(const float2*)&val[(size_t)row * VDIM + kp * 2];
            }
        }
        __syncthreads();

        // ---- Main loop: 32 fma.rn.f32x2 per k-pair per thread ----
        unsigned long long acc[8][4];
        #pragma unroll
        for (int jj = 0; jj < 8; jj++)
            #pragma unroll
            for (int c = 0; c < 4; c++) acc[jj][c] = 0ull;

        const float* vrow = Vs + (size_t)ty * 8 * S;
        const float* wrow = Ws + (size_t)tx * S;

        #pragma unroll 8
        for (int kk = 0; kk < KP; kk++) {
            unsigned long long va[8], wb[4];
            #pragma unroll
            for (int jj = 0; jj < 8; jj++)
                va[jj] = *(const unsigned long long*)(vrow + jj * S + kk * 2);
            #pragma unroll
            for (int c = 0; c < 4; c++)
                wb[c] = *(const unsigned long long*)(wrow + c * 32 * S + kk * 2);
            #pragma unroll
            for (int jj = 0; jj < 8; jj++)
                #pragma unroll
                for (int c = 0; c < 4; c++)
                    asm("fma.rn.f32x2 %0, %1, %2, %0;"
                        : "+l"(acc[jj][c]) : "l"(va[jj]), "l"(wb[c]));
        }

        // ---- Epilogue: fold even/odd-k partials, add bias, scatter rows ----
        float cbr[4];
        #pragma unroll
        for (int c = 0; c < 4; c++) cbr[c] = cb[tx + 32 * c];

        #pragma unroll
        for (int jj = 0; jj < 8; jj++) {
            int row = sIdx[ty * 8 + jj];
            float* orow = out + (size_t)row * NE + ob;
            #pragma unroll
            for (int c = 0; c < 4; c++) {
                float2 p;
                memcpy(&p, &acc[jj][c], 8);
                orow[tx + 32 * c] = p.x + p.y + cbr[c];
            }
        }
    }
}

__global__ void __launch_bounds__(512, 1)
embed_kernel(const float* __restrict__ val, const float* __restrict__ temb,
             const float* __restrict__ w0, const float* __restrict__ b0,
             const float* __restrict__ w1, const float* __restrict__ b1,
             const float* __restrict__ w2, const float* __restrict__ b2,
             const float* __restrict__ w3, const float* __restrict__ b3,
             const float* __restrict__ w4, const float* __restrict__ b4,
             const float* __restrict__ w5, const float* __restrict__ b5,
             float* __restrict__ out)
{
    extern __shared__ float sm[];
    switch (blockIdx.z) {
        case 0: compute_type<32 >(0, val, temb, w0, b0, out, sm); break;
        case 1: compute_type<16 >(1, val, temb, w1, b1, out, sm); break;
        case 2: compute_type<128>(2, val, temb, w2, b2, out, sm); break;
        case 3: compute_type<64 >(3, val, temb, w3, b3, out, sm); break;
        case 4: compute_type<96 >(4, val, temb, w4, b4, out, sm); break;
        case 5: compute_type<1  >(5, val, temb, w5, b5, out, sm); break;
    }
}

extern "C" void kernel_launch(void* const* d_in, const int* in_sizes, int n_in,
                              void* d_out, int out_size) {
    const int*   ttype = (const int*)d_in[0];
    // d_in[1] token_time, d_in[2] token_group: unused by the reference math
    const float* val   = (const float*)d_in[3];
    const float* temb  = (const float*)d_in[4];
    const float* w[6];
    const float* b[6];
    for (int i = 0; i < 6; i++) {
        w[i] = (const float*)d_in[5 + 2 * i];
        b[i] = (const float*)d_in[6 + 2 * i];
    }
    float* out = (float*)d_out;

    // Max smem across templates: D=128 -> S=130: (2*128*130 + 256) floats
    size_t smem = (size_t)(2 * 128 * 130 + 256) * sizeof(float);
    cudaFuncSetAttribute(embed_kernel,
                         cudaFuncAttributeMaxDynamicSharedMemorySize, (int)smem);

    zero_counts_kernel<<<1, 192>>>();
    bucket_kernel<<<NTOK / 256, 256>>>(ttype);

    dim3 grid(TILES_X, NE / OUT_TILE, 6);
    embed_kernel<<<grid, 512, smem>>>(val, temb,
                                      w[0], b[0], w[1], b[1], w[2], b[2],
                                      w[3], b[3], w[4], b[4], w[5], b[5],
                                      out);
}

// round 4
// speedup vs baseline: 1.0070x; 1.0070x over previous
#include <cuda_runtime.h>
#include <cstdint>
#include <cstring>

#define NTOK      65536
#define NE        512
#define VDIM      128
#define TOK_TILE  128
#define OUT_TILE  128
#define TILES_X   88

typedef unsigned long long ull;

// Static scratch (no allocs allowed): bucket lists + padded counters.
__device__ int g_cnt[6 * 32];
__device__ int g_bucket[6][NTOK];

// Known-good pattern from round 1: plain kernel, no symbol queries / memset nodes.
__global__ void zero_counts_kernel() {
    if (threadIdx.x < 6 * 32) g_cnt[threadIdx.x] = 0;
}

// Warp-aggregated bucketing: one atomic per (warp, type) instead of per token.
__global__ void bucket_kernel(const int* __restrict__ ttype) {
    int i = blockIdx.x * blockDim.x + threadIdx.x;   // grid exactly covers NTOK
    int t = ttype[i];
    t = t < 0 ? 0 : (t > 5 ? 5 : t);                 // safety clamp (inputs are 0..5)
    unsigned mask = __match_any_sync(0xffffffffu, t);
    int lane   = threadIdx.x & 31;
    int leader = __ffs(mask) - 1;
    int base = 0;
    if (lane == leader) base = atomicAdd(&g_cnt[t * 32], __popc(mask));
    base = __shfl_sync(mask, base, leader);
    g_bucket[t][base + __popc(mask & ((1u << lane) - 1u))] = i;
}

// ---------------------------------------------------------------------------
// Per-type GEMM. CTA tile: 128 tokens x 128 outputs, 256 threads, 8x8/thread.
// Smem layout (both operands): [group16][kpair][8 rows] of float2, with group
// stride BS = KP*8+2 float2 (= KP*64+16 bytes, ≡16 mod 128) so the 4/8 distinct
// fragment addresses of a warp hit disjoint bank groups (conflict-free, and
// broadcast-deduped across lanes sharing a fragment).
// f32x2 pairs (even k, odd k) partial sums; folded in the epilogue.
// ---------------------------------------------------------------------------
template <int D>
__device__ __forceinline__ void compute_type(
    int t,
    const float* __restrict__ val,
    const float* __restrict__ temb,
    const float* __restrict__ W,
    const float* __restrict__ bias,
    float* __restrict__ out,
    float* sm)
{
    constexpr int KP = (D == 1) ? 1 : D / 2;     // k-pairs
    constexpr int BS = KP * 8 + 2;               // group stride in float2 units

    float2* Vs  = (float2*)sm;                   // [16][BS]
    float2* Ws  = Vs + 16 * BS;                  // [16][BS]
    float*  cb  = (float*)(Ws + 16 * BS);        // [128]
    int*    sIdx = (int*)(cb + OUT_TILE);        // [128]

    const int n = g_cnt[t * 32];
    if (blockIdx.x * TOK_TILE >= n) return;      // uniform per block: safe exit

    const int tid  = threadIdx.x;
    const int lane = tid & 31;
    const int warp = tid >> 5;
    const int tg   = (warp & 3) * 4 + (lane >> 3);   // token group 0..15
    const int og   = (warp >> 2) * 8 + (lane & 7);   // out group 0..15
    const int ob   = blockIdx.y * OUT_TILE;
    const int* __restrict__ bucket = g_bucket[t];

    // ---- W tile + combined bias, loaded once per CTA ----
    if (D == 1) {
        for (int e = tid; e < OUT_TILE; e += 256)
            Ws[(e >> 3) * BS + (e & 7)] = make_float2(W[ob + e], 0.f);
    } else {
        for (int i = tid; i < OUT_TILE * (D / 4); i += 256) {
            int e  = i & 127;
            int kq = i >> 7;
            float4 f = *(const float4*)&W[(size_t)(ob + e) * D + kq * 4];
            float2* blk = Ws + (e >> 3) * BS + (e & 7);
            blk[(2 * kq) * 8]     = make_float2(f.x, f.y);
            blk[(2 * kq + 1) * 8] = make_float2(f.z, f.w);
        }
    }
    for (int e = tid; e < OUT_TILE; e += 256)
        cb[e] = temb[t * NE + ob + e] + bias[ob + e];

    for (int tile = blockIdx.x; tile * TOK_TILE < n; tile += TILES_X) {
        __syncthreads();   // previous iteration's readers done before rewrite

        if (tid < TOK_TILE) {
            int p = tile * TOK_TILE + tid;
            sIdx[tid] = bucket[p < n ? p : 0];
        }
        // ---- Gather value tile (padded lanes duplicate bucket[0]: benign) ----
        if (D == 1) {
            for (int j = tid; j < TOK_TILE; j += 256) {
                int p   = tile * TOK_TILE + j;
                int row = bucket[p < n ? p : 0];
                Vs[(j >> 3) * BS + (j & 7)] = make_float2(val[(size_t)row * VDIM], 0.f);
            }
        } else {
            for (int i = tid; i < TOK_TILE * (D / 4); i += 256) {
                int j  = i & 127;
                int kq = i >> 7;
                int p   = tile * TOK_TILE + j;
                int row = bucket[p < n ? p : 0];
                float4 f = *(const float4*)&val[(size_t)row * VDIM + kq * 4];
                float2* blk = Vs + (j >> 3) * BS + (j & 7);
                blk[(2 * kq) * 8]     = make_float2(f.x, f.y);
                blk[(2 * kq + 1) * 8] = make_float2(f.z, f.w);
            }
        }
        __syncthreads();

        // ---- Main loop: 64 fma.rn.f32x2 per k-pair per thread ----
        ull acc[8][8];
        #pragma unroll
        for (int jj = 0; jj < 8; jj++)
            #pragma unroll
            for (int cc = 0; cc < 8; cc++) acc[jj][cc] = 0ull;

        const float2* aPtr = Vs + tg * BS;
        const float2* bPtr = Ws + og * BS;

        #pragma unroll 2
        for (int kk = 0; kk < KP; kk++) {
            ull va[8], wb[8];
            #pragma unroll
            for (int jj = 0; jj < 8; jj++)
                va[jj] = *(const ull*)(aPtr + kk * 8 + jj);
            #pragma unroll
            for (int cc = 0; cc < 8; cc++)
                wb[cc] = *(const ull*)(bPtr + kk * 8 + cc);
            #pragma unroll
            for (int jj = 0; jj < 8; jj++)
                #pragma unroll
                for (int cc = 0; cc < 8; cc++)
                    asm("fma.rn.f32x2 %0, %1, %2, %0;"
                        : "+l"(acc[jj][cc]) : "l"(va[jj]), "l"(wb[cc]));
        }

        // ---- Epilogue: fold even/odd-k partials, add bias, scatter rows ----
        float cbr[8];
        #pragma unroll
        for (int cc = 0; cc < 8; cc++) cbr[cc] = cb[og * 8 + cc];

        #pragma unroll
        for (int jj = 0; jj < 8; jj++) {
            int row = sIdx[tg * 8 + jj];
            float* orow = out + (size_t)row * NE + ob + og * 8;
            float r[8];
            #pragma unroll
            for (int cc = 0; cc < 8; cc++) {
                float2 p;
                memcpy(&p, &acc[jj][cc], 8);
                r[cc] = p.x + p.y + cbr[cc];
            }
            *(float4*)(orow)     = make_float4(r[0], r[1], r[2], r[3]);
            *(float4*)(orow + 4) = make_float4(r[4], r[5], r[6], r[7]);
        }
    }
}

__global__ void __launch_bounds__(256, 1)
embed_kernel(const float* __restrict__ val, const float* __restrict__ temb,
             const float* __restrict__ w0, const float* __restrict__ b0,
             const float* __restrict__ w1, const float* __restrict__ b1,
             const float* __restrict__ w2, const float* __restrict__ b2,
             const float* __restrict__ w3, const float* __restrict__ b3,
             const float* __restrict__ w4, const float* __restrict__ b4,
             const float* __restrict__ w5, const float* __restrict__ b5,
             float* __restrict__ out)
{
    extern __shared__ float sm[];
    switch (blockIdx.z) {
        case 0: compute_type<32 >(0, val, temb, w0, b0, out, sm); break;
        case 1: compute_type<16 >(1, val, temb, w1, b1, out, sm); break;
        case 2: compute_type<128>(2, val, temb, w2, b2, out, sm); break;
        case 3: compute_type<64 >(3, val, temb, w3, b3, out, sm); break;
        case 4: compute_type<96 >(4, val, temb, w4, b4, out, sm); break;
        case 5: compute_type<1  >(5, val, temb, w5, b5, out, sm); break;
    }
}

extern "C" void kernel_launch(void* const* d_in, const int* in_sizes, int n_in,
                              void* d_out, int out_size) {
    const int*   ttype = (const int*)d_in[0];
    // d_in[1] token_time, d_in[2] token_group: unused by the reference math
    const float* val   = (const float*)d_in[3];
    const float* temb  = (const float*)d_in[4];
    const float* w[6];
    const float* b[6];
    for (int i = 0; i < 6; i++) {
        w[i] = (const float*)d_in[5 + 2 * i];
        b[i] = (const float*)d_in[6 + 2 * i];
    }
    float* out = (float*)d_out;

    // Max smem: D=128 -> KP=64, BS=514 f2: 2*16*514 float2 + 128 f + 128 i
    size_t smem = (size_t)(2 * 16 * 514) * sizeof(float2) + 256 * sizeof(float);
    cudaFuncSetAttribute(embed_kernel,
                         cudaFuncAttributeMaxDynamicSharedMemorySize, (int)smem);

    zero_counts_kernel<<<1, 192>>>();
    bucket_kernel<<<NTOK / 256, 256>>>(ttype);

    dim3 grid(TILES_X, NE / OUT_TILE, 6);
    embed_kernel<<<grid, 256, smem>>>(val, temb,
                                      w[0], b[0], w[1], b[1], w[2], b[2],
                                      w[3], b[3], w[4], b[4], w[5], b[5],
                                      out);
}